// round 12
// baseline (speedup 1.0000x reference)
#include <cuda_runtime.h>
#include <cuda_bf16.h>
#include <cstdint>

// SegmentMM: out[i] = A[i] @ B_eff[segA[i]]
// A:[131072,64] f32, B:[128,64,64] f32, segA int32 sorted, segB int32 perm.
// bf16 3-split (Ah*Bh + Ah*Bl + Al*Bh) on HMMA m16n8k16.
// R12: B fragments RESIDENT in registers (64/thread), loaded once per segment,
// reused across 4x64-row tiles per CTA (256 rows). A raw-f32 cp.async double
// buffer + one bf16 stage per tile. Kills the dominant B-LDSM L1 wavefronts.

#define S_SEG 128
#define TILES 4

__device__ __align__(16) unsigned char d_Bh[S_SEG * 8192];
__device__ __align__(16) unsigned char d_Bl[S_SEG * 8192];

__device__ __forceinline__ uint32_t sw128(uint32_t off) {
    return off ^ ((off >> 3) & 0x70);
}

__device__ __forceinline__ void cvt_split4(float4 v, uint2& hi, uint2& lo) {
    __nv_bfloat162 h01 = __floats2bfloat162_rn(v.x, v.y);
    __nv_bfloat162 h23 = __floats2bfloat162_rn(v.z, v.w);
    float rx = v.x - __bfloat162float(h01.x);
    float ry = v.y - __bfloat162float(h01.y);
    float rz = v.z - __bfloat162float(h23.x);
    float rw = v.w - __bfloat162float(h23.y);
    __nv_bfloat162 l01 = __floats2bfloat162_rn(rx, ry);
    __nv_bfloat162 l23 = __floats2bfloat162_rn(rz, rw);
    hi = make_uint2(*(uint32_t*)&h01, *(uint32_t*)&h23);
    lo = make_uint2(*(uint32_t*)&l01, *(uint32_t*)&l23);
}

// ---- B pre-split kernel: block j converts B[j] -> d_Bh/d_Bl[segB[j]] ----
__global__ __launch_bounds__(256)
void presplit_B_kernel(const float* __restrict__ B,
                       const int* __restrict__ segB)
{
    const int j = blockIdx.x;
    const int s = segB[j];
    const int tid = threadIdx.x;
    const float4* B4 = (const float4*)(B + (size_t)j * 4096);
    unsigned char* bh = d_Bh + (size_t)s * 8192;
    unsigned char* bl = d_Bl + (size_t)s * 8192;
    #pragma unroll
    for (int it = 0; it < 4; ++it) {
        int i = it * 256 + tid;
        float4 v = B4[i];
        int k = i >> 4, mq = i & 15;
        uint32_t sw = sw128((uint32_t)(k * 128 + mq * 8));
        uint2 hi, lo;
        cvt_split4(v, hi, lo);
        *(uint2*)(bh + sw) = hi;
        *(uint2*)(bl + sw) = lo;
    }
}

// ---- main kernel smem ----
// Araw double buffer (f32, 64x64, linear 256B rows): 16KB x2
// Ah/Al bf16 SW128: 8KB x2 ; Bh/Bl bf16 SW128: 8KB x2
#define SM_AR0 0
#define SM_AR1 16384
#define SM_AH  32768
#define SM_AL  40960
#define SM_BH  49152
#define SM_BL  57344
#define SMEM_TOTAL 65536

__device__ __forceinline__ uint32_t smem_u32(const void* p) {
    uint32_t a;
    asm("{ .reg .u64 t; cvta.to.shared.u64 t, %1; cvt.u32.u64 %0, t; }"
        : "=r"(a) : "l"(p));
    return a;
}
__device__ __forceinline__ void ldsm_x4(uint32_t& r0, uint32_t& r1,
                                        uint32_t& r2, uint32_t& r3, uint32_t a) {
    asm volatile("ldmatrix.sync.aligned.m8n8.x4.shared.b16 {%0,%1,%2,%3}, [%4];"
                 : "=r"(r0), "=r"(r1), "=r"(r2), "=r"(r3) : "r"(a));
}
__device__ __forceinline__ void ldsm_x4t(uint32_t& r0, uint32_t& r1,
                                         uint32_t& r2, uint32_t& r3, uint32_t a) {
    asm volatile("ldmatrix.sync.aligned.m8n8.x4.trans.shared.b16 {%0,%1,%2,%3}, [%4];"
                 : "=r"(r0), "=r"(r1), "=r"(r2), "=r"(r3) : "r"(a));
}
__device__ __forceinline__ void mma16816(float* d, const uint32_t* a,
                                         uint32_t b0, uint32_t b1) {
    asm volatile(
        "mma.sync.aligned.m16n8k16.row.col.f32.bf16.bf16.f32 "
        "{%0,%1,%2,%3}, {%4,%5,%6,%7}, {%8,%9}, {%0,%1,%2,%3};"
        : "+f"(d[0]), "+f"(d[1]), "+f"(d[2]), "+f"(d[3])
        : "r"(a[0]), "r"(a[1]), "r"(a[2]), "r"(a[3]), "r"(b0), "r"(b1));
}
#define CP_ASYNC16(dst, src)                                                   \
    asm volatile("cp.async.cg.shared.global [%0], [%1], 16;"                   \
                 :: "r"(dst), "l"(src) : "memory")
#define CP_COMMIT  asm volatile("cp.async.commit_group;" ::: "memory")
#define CP_WAIT0   asm volatile("cp.async.wait_group 0;" ::: "memory")
#define CP_WAIT1   asm volatile("cp.async.wait_group 1;" ::: "memory")

__global__ __launch_bounds__(256, 2)
void segmm_hmma_kernel(const float* __restrict__ A,
                       const int* __restrict__ segA,
                       float* __restrict__ out)
{
    extern __shared__ __align__(128) unsigned char smem[];
    const uint32_t sb   = smem_u32(smem);
    const int tid   = threadIdx.x;
    const int w     = tid >> 5;          // 0..7
    const int lane  = tid & 31;
    const int r0    = blockIdx.x * (TILES * 64);
    const int wrow  = (w & 3) * 16;      // row group within tile
    const int whalf = (w >> 2);          // N half

    const int rA = wrow + (lane >> 2);
    const int rB = rA + 8;
    const int cb = (lane & 3) * 2;

    const uint32_t a_row = (uint32_t)(wrow + (lane & 15));
    const uint32_t a_sel = (uint32_t)(lane >> 4) * 16;
    const uint32_t b_row = (uint32_t)(lane & 15);
    const uint32_t b_nt  = (uint32_t)(lane >> 4);
    const uint32_t ntb   = (uint32_t)whalf * 4;

    // ---- initial async loads: G0={Araw(0), B(s0)}, G1={Araw(1)} ----
    {
        const unsigned char* gA = (const unsigned char*)(A + (size_t)r0 * 64);
        #pragma unroll
        for (int it = 0; it < 4; ++it) {
            uint32_t off = (uint32_t)(it * 256 + tid) * 16;
            CP_ASYNC16(sb + SM_AR0 + off, gA + off);
        }
    }
    int s_smem = segA[r0];               // segment currently in B smem
    {
        const unsigned char* gh = d_Bh + (size_t)s_smem * 8192;
        const unsigned char* gl = d_Bl + (size_t)s_smem * 8192;
        #pragma unroll
        for (int it = 0; it < 2; ++it) {
            uint32_t off = (uint32_t)(it * 256 + tid) * 16;
            CP_ASYNC16(sb + SM_BH + off, gh + off);
            CP_ASYNC16(sb + SM_BL + off, gl + off);
        }
        CP_COMMIT;                        // G0
    }
    {
        const unsigned char* gA = (const unsigned char*)(A + (size_t)(r0 + 64) * 64);
        #pragma unroll
        for (int it = 0; it < 4; ++it) {
            uint32_t off = (uint32_t)(it * 256 + tid) * 16;
            CP_ASYNC16(sb + SM_AR1 + off, gA + off);
        }
        CP_COMMIT;                        // G1
    }

    // resident B fragments for this warp's N-half
    uint32_t bhf[4][8], blf[4][8];
    int s_cur = -1;                       // segment currently in registers

    #pragma unroll 1
    for (int t = 0; t < TILES; ++t) {
        const int tr0 = r0 + t * 64;

        if (t < TILES - 1) { CP_WAIT1; } else { CP_WAIT0; }
        __syncthreads();                  // Araw(t) ready; prev compute done

        // ---- stage A(t): Araw f32 -> Ah/Al bf16 SW128 ----
        {
            const uint32_t src = sb + ((t & 1) ? SM_AR1 : SM_AR0);
            #pragma unroll
            for (int it = 0; it < 4; ++it) {
                int i = it * 256 + tid;          // 0..1023 float4s
                float4 v;
                asm volatile("ld.shared.v4.f32 {%0,%1,%2,%3}, [%4];"
                             : "=f"(v.x), "=f"(v.y), "=f"(v.z), "=f"(v.w)
                             : "r"(src + (uint32_t)i * 16));
                int r = i >> 4, kq = i & 15;
                uint32_t sw = sw128((uint32_t)(r * 128 + kq * 8));
                uint2 hi, lo;
                cvt_split4(v, hi, lo);
                *(uint2*)(smem + SM_AH + sw) = hi;
                *(uint2*)(smem + SM_AL + sw) = lo;
            }
        }
        __syncthreads();                  // Ah/Al ready; Araw(t) free

        // prefetch Araw(t+2) into the freed buffer
        if (t + 2 < TILES) {
            const uint32_t dst = sb + ((t & 1) ? SM_AR1 : SM_AR0);
            const unsigned char* gA =
                (const unsigned char*)(A + (size_t)(tr0 + 128) * 64);
            #pragma unroll
            for (int it = 0; it < 4; ++it) {
                uint32_t off = (uint32_t)(it * 256 + tid) * 16;
                CP_ASYNC16(dst + off, gA + off);
            }
            CP_COMMIT;
        }

        const int seg0 = segA[tr0 + rA];
        const int seg1 = segA[tr0 + rB];
        const int sLoT = segA[tr0];
        const int sHiT = segA[tr0 + 63];

        for (int s = sLoT; s <= sHiT; ++s) {
            if (s != s_smem) {            // CTA-uniform: fetch new B tile
                __syncthreads();
                const unsigned char* gh = d_Bh + (size_t)s * 8192;
                const unsigned char* gl = d_Bl + (size_t)s * 8192;
                #pragma unroll
                for (int it = 0; it < 2; ++it) {
                    uint32_t off = (uint32_t)(it * 256 + tid) * 16;
                    CP_ASYNC16(sb + SM_BH + off, gh + off);
                    CP_ASYNC16(sb + SM_BL + off, gl + off);
                }
                CP_COMMIT;
                CP_WAIT0;                 // also drains A prefetch (rare)
                __syncthreads();
                s_smem = s;
            }

            bool ok0 = (seg0 == s);
            bool ok1 = (seg1 == s);
            if (__ballot_sync(0xffffffffu, ok0 || ok1) == 0u) continue;

            if (s != s_cur) {             // per-warp: refresh resident B frags
                #pragma unroll
                for (int kk = 0; kk < 4; ++kk) {
                    uint32_t roff = ((uint32_t)(kk * 16) + b_row) * 128;
                    #pragma unroll
                    for (int ntp = 0; ntp < 2; ++ntp) {
                        uint32_t sw = sw128(roff + (ntb + (uint32_t)(ntp * 2) + b_nt) * 16);
                        ldsm_x4t(bhf[kk][ntp * 4 + 0], bhf[kk][ntp * 4 + 1],
                                 bhf[kk][ntp * 4 + 2], bhf[kk][ntp * 4 + 3],
                                 sb + SM_BH + sw);
                        ldsm_x4t(blf[kk][ntp * 4 + 0], blf[kk][ntp * 4 + 1],
                                 blf[kk][ntp * 4 + 2], blf[kk][ntp * 4 + 3],
                                 sb + SM_BL + sw);
                    }
                }
                s_cur = s;
            }

            float acc[4][4];
            #pragma unroll
            for (int nt = 0; nt < 4; ++nt)
                #pragma unroll
                for (int q = 0; q < 4; ++q) acc[nt][q] = 0.f;

            #pragma unroll
            for (int kk = 0; kk < 4; ++kk) {
                uint32_t asw = sw128(a_row * 128 + (uint32_t)(kk * 32) + a_sel);
                uint32_t ah[4], al[4];
                ldsm_x4(ah[0], ah[1], ah[2], ah[3], sb + SM_AH + asw);
                ldsm_x4(al[0], al[1], al[2], al[3], sb + SM_AL + asw);
                mma16816(acc[0], ah, bhf[kk][0], bhf[kk][1]);
                mma16816(acc[1], ah, bhf[kk][2], bhf[kk][3]);
                mma16816(acc[2], ah, bhf[kk][4], bhf[kk][5]);
                mma16816(acc[3], ah, bhf[kk][6], bhf[kk][7]);
                mma16816(acc[0], ah, blf[kk][0], blf[kk][1]);
                mma16816(acc[1], ah, blf[kk][2], blf[kk][3]);
                mma16816(acc[2], ah, blf[kk][4], blf[kk][5]);
                mma16816(acc[3], ah, blf[kk][6], blf[kk][7]);
                mma16816(acc[0], al, bhf[kk][0], bhf[kk][1]);
                mma16816(acc[1], al, bhf[kk][2], bhf[kk][3]);
                mma16816(acc[2], al, bhf[kk][4], bhf[kk][5]);
                mma16816(acc[3], al, bhf[kk][6], bhf[kk][7]);
            }

            float* o0 = out + (size_t)(tr0 + rA) * 64 + whalf * 32 + cb;
            float* o1 = out + (size_t)(tr0 + rB) * 64 + whalf * 32 + cb;
            #pragma unroll
            for (int nt = 0; nt < 4; ++nt) {
                if (ok0) *(float2*)(o0 + nt * 8) = make_float2(acc[nt][0], acc[nt][1]);
                if (ok1) *(float2*)(o1 + nt * 8) = make_float2(acc[nt][2], acc[nt][3]);
            }
        }
    }
}

extern "C" void kernel_launch(void* const* d_in, const int* in_sizes, int n_in,
                              void* d_out, int out_size) {
    const float* A    = (const float*)d_in[0];
    const float* B    = (const float*)d_in[1];
    const int*   segA = (const int*)d_in[2];
    const int*   segB = (const int*)d_in[3];
    float* out = (float*)d_out;

    const int N = in_sizes[0] / 64;      // 131072
    const int S = in_sizes[3];           // 128

    cudaFuncSetAttribute(segmm_hmma_kernel,
                         cudaFuncAttributeMaxDynamicSharedMemorySize, SMEM_TOTAL);

    presplit_B_kernel<<<S, 256>>>(B, segB);
    segmm_hmma_kernel<<<N / (TILES * 64), 256, SMEM_TOTAL>>>(A, segA, out);
}